// round 13
// baseline (speedup 1.0000x reference)
#include <cuda_runtime.h>
#include <cuda_fp16.h>
#include <math.h>

#define NB 2
#define NE 512
#define NH 8
#define ND 64
#define NT 2048
#define EPSV 1e-5f
// exp(s/181) = ex2(s * log2(e)/181); folded into Q at projection time
#define EXP_C (1.44269504088896341f/181.0f)

// ---------------- scratch (device globals: allocation-free) ----------------
__device__ __half g_Wh[4*NE*NE];        // standardized weights, half, [mat][m][e]
__device__ __half g_xT[3*NB*NT*NE];     // masked transposed inputs [which][b][t][e]
__device__ __half g_qh[NB*NH*NT*ND];    // Q transposed (pre-scaled by EXP_C): [b][h][t][d]
__device__ __half g_kh[NB*NH*NT*ND];    // K transposed: [b][h][t][d]
__device__ __half g_vh[NB*NE*NT];       // V (key-masked): [b][e][t]
__device__ __half g_kmh[NB*NT];         // key_mask as half
__device__ __half g_aT[NB*NT*NE];       // attention out transposed [b][t][e]

__device__ __forceinline__ float ex2a(float x) {
    float y;
    asm("ex2.approx.f32 %0, %1;" : "=f"(y) : "f"(x));
    return y;
}
// pack two fp32 -> half2 (lo = first arg)
__device__ __forceinline__ unsigned packh2(float lo, float hi) {
    unsigned r;
    asm("cvt.rn.f16x2.f32 %0, %1, %2;" : "=r"(r) : "f"(hi), "f"(lo));
    return r;
}
__device__ __forceinline__ void mma_f16(float* d,
        unsigned a0, unsigned a1, unsigned a2, unsigned a3,
        unsigned b0, unsigned b1) {
    asm volatile("mma.sync.aligned.m16n8k16.row.col.f32.f16.f16.f32 "
        "{%0,%1,%2,%3}, {%4,%5,%6,%7}, {%8,%9}, {%0,%1,%2,%3};\n"
        : "+f"(d[0]), "+f"(d[1]), "+f"(d[2]), "+f"(d[3])
        : "r"(a0), "r"(a1), "r"(a2), "r"(a3), "r"(b0), "r"(b1));
}
__device__ __forceinline__ void ldsm4(unsigned& r0, unsigned& r1, unsigned& r2, unsigned& r3,
                                      unsigned a) {
    asm volatile("ldmatrix.sync.aligned.m8n8.x4.shared.b16 {%0,%1,%2,%3}, [%4];"
        : "=r"(r0), "=r"(r1), "=r"(r2), "=r"(r3) : "r"(a));
}
__device__ __forceinline__ void ldsm2(unsigned& r0, unsigned& r1, unsigned a) {
    asm volatile("ldmatrix.sync.aligned.m8n8.x2.shared.b16 {%0,%1}, [%2];"
        : "=r"(r0), "=r"(r1) : "r"(a));
}
__device__ __forceinline__ void cp16(void* dst, const void* src) {
    unsigned d = (unsigned)__cvta_generic_to_shared(dst);
    asm volatile("cp.async.ca.shared.global [%0], [%1], 16;" :: "r"(d), "l"(src));
}
__device__ __forceinline__ void cp_commit() { asm volatile("cp.async.commit_group;"); }
__device__ __forceinline__ void cp_wait0()  { asm volatile("cp.async.wait_group 0;"); }

// ---------------- 1) weight standardization (writes half) ----------------
__global__ void std_weights_kernel(const float* __restrict__ W0, const float* __restrict__ W1,
                                   const float* __restrict__ W2, const float* __restrict__ W3) {
    const float* Ws[4] = {W0, W1, W2, W3};
    const float* W = Ws[blockIdx.y];
    __half* out = g_Wh + blockIdx.y * NE * NE;
    const int row = blockIdx.x;
    const int tid = threadIdx.x;

    float w[4];
    #pragma unroll
    for (int j = 0; j < 4; j++) w[j] = W[row*NE + tid + 128*j];

    __shared__ float red[4];
    float s = w[0]+w[1]+w[2]+w[3];
    #pragma unroll
    for (int o = 16; o > 0; o >>= 1) s += __shfl_down_sync(0xffffffffu, s, o);
    if ((tid & 31) == 0) red[tid >> 5] = s;
    __syncthreads();
    const float mu = (red[0]+red[1]+red[2]+red[3]) * (1.0f/NE);
    __syncthreads();

    float s2 = 0.f;
    #pragma unroll
    for (int j = 0; j < 4; j++) { float d = w[j]-mu; s2 += d*d; }
    #pragma unroll
    for (int o = 16; o > 0; o >>= 1) s2 += __shfl_down_sync(0xffffffffu, s2, o);
    if ((tid & 31) == 0) red[tid >> 5] = s2;
    __syncthreads();
    const float var = (red[0]+red[1]+red[2]+red[3]) * (1.0f/NE);
    const float rstd = rsqrtf(var + EPSV);
    #pragma unroll
    for (int j = 0; j < 4; j++)
        out[row*NE + tid + 128*j] = __float2half_rn((w[j]-mu)*rstd);
}

// ---------------- 1b) masked transpose + mask-to-half ----------------
__global__ void transpose_mask_kernel(const float* __restrict__ x0, const float* __restrict__ x1,
                                      const float* __restrict__ x2,
                                      const int* __restrict__ m0, const int* __restrict__ m1,
                                      const int* __restrict__ m2) {
    const int which = blockIdx.z >> 1;
    const int b = blockIdx.z & 1;
    const float* X = (which == 0) ? x0 : (which == 1) ? x1 : x2;
    const int*   M = (which == 0) ? m0 : (which == 1) ? m1 : m2;
    __half* O = g_xT + ((size_t)which*NB + b)*NT*NE;

    __shared__ float tile[32][33];
    const int t0 = blockIdx.x*32, e0 = blockIdx.y*32;
    const int tx = threadIdx.x, ty = threadIdx.y;
    #pragma unroll
    for (int i = 0; i < 4; i++)
        tile[ty+8*i][tx] = X[(size_t)(b*NE + e0 + ty + 8*i)*NT + t0 + tx];
    __syncthreads();
    #pragma unroll
    for (int i = 0; i < 4; i++) {
        const int t = t0 + ty + 8*i;
        const float mk = (float)M[b*NT + t];
        O[(size_t)t*NE + e0 + tx] = __float2half_rn(tile[tx][ty+8*i]*mk);
    }
}

__global__ void mask_half_kernel(const int* __restrict__ km) {
    const int i = blockIdx.x*256 + threadIdx.x;
    g_kmh[i] = __float2half_rn((float)km[i]);
}

// ---------------- 2/4) projection GEMM: fp16 mma + ldmatrix, BK=128, 2-stage ----------------
// mode 1: LN*oscale + transposed half out [b][h][t][64]  (Q: oscale=EXP_C; K: 1)
// mode 2: LN * key_mask + half out [b][e][t]             (V)
// mode 0: fp32 out [b][e][t] + bias                      (final output)
struct ProjSet {
    const __half* bT; const __half* wh; const float* bias;
    const float* lng; const float* lnb; void* out; int mode;
    float oscale; const int* xmask;
};
struct ProjArgs { ProjSet s[3]; };

// BK=128 halves: tile rows hold 128 halves (256B) padded to 272B (68 u32) — LDSM conflict-free
#define PR_S 68
#define WST (64*PR_S)            // per W stage (u32)
#define XST (128*PR_S)           // per x stage (u32)
#define XT_S 136
#define PROJ_SMEM ((2*WST + 2*XST)*4)   // 104448 B (covers LN tile 64*136*4 too)

template<bool DO_LN>
__global__ void __launch_bounds__(256) proj_h_kernel(ProjArgs A) {
    const int which = blockIdx.z >> 1;
    const int b = blockIdx.z & 1;
    const __half* __restrict__ Bt = A.s[which].bT + (size_t)b*NT*NE;
    const __half* __restrict__ Wh = A.s[which].wh;
    const float*  __restrict__ Bp = A.s[which].bias;
    const float*  __restrict__ Gp = A.s[which].lng;
    const float*  __restrict__ Lp = A.s[which].lnb;
    void*         __restrict__ Op = A.s[which].out;

    const int h  = blockIdx.y;
    const int t0 = blockIdx.x * 128;
    const int tid = threadIdx.x;
    const int lane = tid & 31;
    const int wid = tid >> 5;
    const int wm = wid & 1, wn = wid >> 1;
    const int g = lane >> 2, t4 = lane & 3;

    extern __shared__ float psm[];
    unsigned* wtb = (unsigned*)psm;        // [2][WST]
    unsigned* xtb = wtb + 2*WST;           // [2][XST]
    __shared__ float lng_s[ND];
    __shared__ float lnb_s[ND];
    __shared__ float red_s[256];

    if (DO_LN && tid < 64) {
        lng_s[tid] = Gp[tid];
        lnb_s[tid] = Lp[tid];
    }

    const __half* Wr = Wh + (size_t)(h*ND)*NE;

    auto prefetch = [&](int c, int s) {
        const int k0 = c*128;
        #pragma unroll
        for (int l = 0; l < 4; l++) {   // W: 64 rows x 256B = 1024 cp16
            int idx = tid + 256*l; int r = idx >> 4, c16 = idx & 15;
            cp16((char*)(wtb + s*WST + r*PR_S) + c16*16, Wr + (size_t)r*NE + k0 + c16*8);
        }
        #pragma unroll
        for (int l = 0; l < 8; l++) {   // x: 128 rows x 256B = 2048 cp16
            int idx = tid + 256*l; int r = idx >> 4, c16 = idx & 15;
            cp16((char*)(xtb + s*XST + r*PR_S) + c16*16, Bt + (size_t)(t0 + r)*NE + k0 + c16*8);
        }
    };

    prefetch(0, 0);
    cp_commit();

    // ldmatrix lane->address maps (272B row stride: conflict-free)
    const unsigned w_sh = (unsigned)__cvta_generic_to_shared(wtb);
    const unsigned x_sh = (unsigned)__cvta_generic_to_shared(xtb);
    const unsigned aoff = (unsigned)(((((lane>>3)&1)*8) + (lane&7))*272 + ((lane>>4)&1)*16);
    const unsigned boff = (unsigned)(((((lane>>4)&1)*8) + (lane&7))*272 + ((lane>>3)&1)*16);

    float acc[2][4][4];
    #pragma unroll
    for (int mt = 0; mt < 2; mt++)
        #pragma unroll
        for (int n = 0; n < 4; n++)
            #pragma unroll
            for (int j = 0; j < 4; j++) acc[mt][n][j] = 0.f;

    for (int c = 0; c < 4; c++) {
        const int cur = c & 1;
        cp_wait0();
        __syncthreads();
        if (c + 1 < 4) { prefetch(c+1, cur^1); cp_commit(); }

        const unsigned wb = w_sh + cur*(WST*4);
        const unsigned xb = x_sh + cur*(XST*4);
        #pragma unroll
        for (int sub = 0; sub < 8; sub++) {
            unsigned a[2][4];
            #pragma unroll
            for (int mt = 0; mt < 2; mt++)
                ldsm4(a[mt][0], a[mt][1], a[mt][2], a[mt][3],
                      wb + (wm*32 + mt*16)*272 + sub*32 + aoff);
            #pragma unroll
            for (int ng = 0; ng < 2; ng++) {
                unsigned b0a, b1a, b0b, b1b;
                ldsm4(b0a, b1a, b0b, b1b, xb + (wn*32 + ng*16)*272 + sub*32 + boff);
                #pragma unroll
                for (int mt = 0; mt < 2; mt++) {
                    mma_f16(acc[mt][ng*2  ], a[mt][0], a[mt][1], a[mt][2], a[mt][3], b0a, b1a);
                    mma_f16(acc[mt][ng*2+1], a[mt][0], a[mt][1], a[mt][2], a[mt][3], b0b, b1b);
                }
            }
        }
    }

    float bv[2][2];
    #pragma unroll
    for (int mt = 0; mt < 2; mt++) {
        bv[mt][0] = Bp[h*ND + wm*32 + mt*16 + g];
        bv[mt][1] = Bp[h*ND + wm*32 + mt*16 + g + 8];
    }

    if (!DO_LN) {
        float* o = (float*)Op + (size_t)(b*NE + h*ND)*NT + t0;
        #pragma unroll
        for (int mt = 0; mt < 2; mt++) {
            const int r0 = wm*32 + mt*16 + g;
            #pragma unroll
            for (int n = 0; n < 4; n++) {
                const int cc = wn*32 + n*8 + 2*t4;
                *(float2*)(o + (size_t)(r0  )*NT + cc) =
                    make_float2(acc[mt][n][0] + bv[mt][0], acc[mt][n][1] + bv[mt][0]);
                *(float2*)(o + (size_t)(r0+8)*NT + cc) =
                    make_float2(acc[mt][n][2] + bv[mt][1], acc[mt][n][3] + bv[mt][1]);
            }
        }
    } else {
        __syncthreads();   // done with pipeline buffers; reuse psm as [64][136] fp32 tile
        #pragma unroll
        for (int mt = 0; mt < 2; mt++) {
            const int r0 = wm*32 + mt*16 + g;
            #pragma unroll
            for (int n = 0; n < 4; n++) {
                const int cc = wn*32 + n*8 + 2*t4;
                *(float2*)(psm + (r0  )*XT_S + cc) =
                    make_float2(acc[mt][n][0] + bv[mt][0], acc[mt][n][1] + bv[mt][0]);
                *(float2*)(psm + (r0+8)*XT_S + cc) =
                    make_float2(acc[mt][n][2] + bv[mt][1], acc[mt][n][3] + bv[mt][1]);
            }
        }
        __syncthreads();
        // parallel LN: 256 threads, thread owns 32 rows of column cc
        const int cc = tid & 127, hf = tid >> 7;
        const int d0 = hf*32;
        float s = 0.f;
        #pragma unroll 8
        for (int d = 0; d < 32; d++) s += psm[(d0+d)*XT_S + cc];
        red_s[tid] = s;
        __syncthreads();
        const float mu = (red_s[cc] + red_s[128+cc]) * (1.0f/64.0f);
        __syncthreads();
        float s2 = 0.f;
        #pragma unroll 8
        for (int d = 0; d < 32; d++) { float dd = psm[(d0+d)*XT_S + cc] - mu; s2 += dd*dd; }
        red_s[tid] = s2;
        __syncthreads();
        const float rstd = rsqrtf((red_s[cc] + red_s[128+cc])*(1.0f/64.0f) + EPSV);
        const int mode = A.s[which].mode;
        if (mode == 1) {
            const float osc = A.s[which].oscale;
            __half2* dst = (__half2*)((__half*)Op + ((size_t)((b*NH + h)*NT) + t0 + cc)*64);
            #pragma unroll 8
            for (int d2 = hf*16; d2 < hf*16 + 16; d2++) {
                float x0 = ((psm[(2*d2  )*XT_S + cc] - mu)*rstd*lng_s[2*d2  ] + lnb_s[2*d2  ])*osc;
                float x1 = ((psm[(2*d2+1)*XT_S + cc] - mu)*rstd*lng_s[2*d2+1] + lnb_s[2*d2+1])*osc;
                dst[d2] = __floats2half2_rn(x0, x1);
            }
        } else {
            // V: multiply by key_mask so attention needs no score masking
            const float kmv = (float)A.s[which].xmask[b*NT + t0 + cc];
            __half* dst = (__half*)Op + (size_t)(b*NE + h*ND)*NT + t0 + cc;
            #pragma unroll 8
            for (int d = d0; d < d0 + 32; d++)
                dst[(size_t)d*NT] =
                    __float2half_rn(((psm[d*XT_S + cc] - mu)*rstd*lng_s[d] + lnb_s[d])*kmv);
        }
    }
}

// ---------------- 3) flash attention: fp16 mma + ldmatrix + rs-by-matmul ----------------
// grid (T/128, H, B), 256 thr = 8 warps; warp w owns q-rows [w*16, w*16+16).
// K tile: 64 rows x 72 halves (row=key, col=d). V tile: 72 rows x 72 halves
// (rows 0..63 = d, row 64 = key_mask, rows 65..71 = 0); stride 144B => LDSM conflict-free.
// Q pre-scaled by log2e/181 => p = ex2(sf) directly; V key-masked => no score mask;
// oacc n-tile 8 col 64 accumulates the softmax denominator.
#define KV_S2 36
#define KTILE (64*KV_S2)
#define VTILE (72*KV_S2)

__global__ void __launch_bounds__(256, 2) attn_mma_kernel(
        const __half* __restrict__ qh, const __half* __restrict__ kh, const __half* __restrict__ vh,
        const __half* __restrict__ kmh, const int* __restrict__ qmask,
        __half* __restrict__ aT) {
    __shared__ unsigned kh2[2*KTILE];
    __shared__ unsigned vh2[2*VTILE];

    const int t0 = blockIdx.x * 128;
    const int h = blockIdx.y, b = blockIdx.z;
    const int tid = threadIdx.x;
    const int lane = tid & 31;
    const int w = tid >> 5;
    const int g = lane >> 2;
    const int t4 = lane & 3;
    const int w16 = w * 16;
    const int base  = (b*NE + h*ND)*NT;
    const int baseq = ((b*NH + h)*NT);

    // zero V rows 65..71 (both stages) — never touched by cp.async afterwards
    for (int i = tid; i < 2*7*KV_S2; i += 256) {
        int s = i / (7*KV_S2), r = i - s*(7*KV_S2);
        vh2[s*VTILE + 65*KV_S2 + r] = 0;
    }

    // Q fragments straight from gmem (transposed [t][64], pre-scaled)
    const __half* q0 = qh + (size_t)(baseq + t0 + w16 + g)*64;
    const __half* q1 = q0 + 8*64;
    unsigned qa[4][4];
    #pragma unroll
    for (int kc = 0; kc < 4; kc++) {
        qa[kc][0] = *(const unsigned*)(q0 + 16*kc + 2*t4);
        qa[kc][1] = *(const unsigned*)(q1 + 16*kc + 2*t4);
        qa[kc][2] = *(const unsigned*)(q0 + 16*kc + 2*t4 + 8);
        qa[kc][3] = *(const unsigned*)(q1 + 16*kc + 2*t4 + 8);
    }

    auto prefetch = [&](int kt, int s) {
        const int tk0 = kt*64;
        #pragma unroll
        for (int l = 0; l < 2; l++) {
            int idx = tid + 256*l;
            int row = idx >> 3, c16 = idx & 7;
            cp16((char*)(kh2 + s*KTILE + row*KV_S2) + c16*16,
                 kh + (size_t)(baseq + tk0 + row)*64 + c16*8);
            cp16((char*)(vh2 + s*VTILE + row*KV_S2) + c16*16,
                 vh + (size_t)(base + row*NT) + tk0 + c16*8);
        }
        if (tid < 8)
            cp16((char*)(vh2 + s*VTILE + 64*KV_S2) + tid*16, kmh + b*NT + tk0 + tid*8);
    };

    prefetch(0, 0);
    cp_commit();

    const unsigned ks_sh = (unsigned)__cvta_generic_to_shared(kh2);
    const unsigned vs_sh = (unsigned)__cvta_generic_to_shared(vh2);
    const int mm = lane >> 3, rr = lane & 7;
    const unsigned rowoff  = (unsigned)((((mm>>1)*8 + rr)*144) + (mm&1)*16);
    const unsigned rowoff2 = (unsigned)(((64 + rr)*144) + (mm&1)*16);

    float oacc[9][4];
    #pragma unroll
    for (int n = 0; n < 9; n++)
        #pragma unroll
        for (int j = 0; j < 4; j++) oacc[n][j] = 0.f;

    for (int kt = 0; kt < NT/64; kt++) {
        const int cur = kt & 1;
        cp_wait0();
        __syncthreads();
        if (kt + 1 < NT/64) { prefetch(kt+1, cur^1); cp_commit(); }

        const unsigned ksb = ks_sh + cur*KTILE*4 + rowoff;
        const unsigned vsb = vs_sh + cur*VTILE*4;

        // ---- S = Q K^T (scaled) ----
        float sf[8][4];
        #pragma unroll
        for (int n = 0; n < 8; n++)
            #pragma unroll
            for (int j = 0; j < 4; j++) sf[n][j] = 0.f;
        #pragma unroll
        for (int kc = 0; kc < 4; kc++) {
            #pragma unroll
            for (int j = 0; j < 4; j++) {
                unsigned b0a, b1a, b0b, b1b;
                ldsm4(b0a, b1a, b0b, b1b, ksb + j*2304 + kc*32);
                mma_f16(sf[2*j  ], qa[kc][0], qa[kc][1], qa[kc][2], qa[kc][3], b0a, b1a);
                mma_f16(sf[2*j+1], qa[kc][0], qa[kc][1], qa[kc][2], qa[kc][3], b0b, b1b);
            }
        }

        // ---- p = ex2(sf) (unmasked; V carries the mask), pack to A fragments ----
        unsigned plo[8], phi[8];
        #pragma unroll
        for (int n = 0; n < 8; n++) {
            plo[n] = packh2(ex2a(sf[n][0]), ex2a(sf[n][1]));
            phi[n] = packh2(ex2a(sf[n][2]), ex2a(sf[n][3]));
        }

        // ---- O += P V^T (+ mask-row tile accumulates denominator) ----
        #pragma unroll
        for (int kc = 0; kc < 4; kc++) {
            unsigned a0 = plo[2*kc], a1 = phi[2*kc], a2 = plo[2*kc+1], a3 = phi[2*kc+1];
            #pragma unroll
            for (int j = 0; j < 4; j++) {
                unsigned b0a, b1a, b0b, b1b;
                ldsm4(b0a, b1a, b0b, b1b, vsb + rowoff + j*2304 + kc*32);
                mma_f16(oacc[2*j  ], a0, a1, a2, a3, b0a, b1a);
                mma_f16(oacc[2*j+1], a0, a1, a2, a3, b0b, b1b);
            }
            unsigned m0, m1;
            ldsm2(m0, m1, vsb + rowoff2 + kc*32);
            mma_f16(oacc[8], a0, a1, a2, a3, m0, m1);
        }
    }

    // ---- denominator from mask-tile col 64 (t4==0 slot), broadcast in quad ----
    const float rs0 = __shfl_sync(0xffffffffu, oacc[8][0], lane & ~3);
    const float rs1 = __shfl_sync(0xffffffffu, oacc[8][2], lane & ~3);

    const int qrow0 = t0 + w16 + g;
    const int qrow1 = qrow0 + 8;
    const float sel0 = (qmask[b*NT + qrow0] != 0) ? (1.0f / rs0) : 0.f;
    const float sel1 = (qmask[b*NT + qrow1] != 0) ? (1.0f / rs1) : 0.f;
    __half* o0 = aT + (size_t)(b*NT + qrow0)*NE + h*ND;
    __half* o1 = aT + (size_t)(b*NT + qrow1)*NE + h*ND;
    #pragma unroll
    for (int n = 0; n < 8; n++) {
        const int d0 = n*8 + 2*t4;
        *(unsigned*)(o0 + d0) = packh2(oacc[n][0]*sel0, oacc[n][1]*sel0);
        *(unsigned*)(o1 + d0) = packh2(oacc[n][2]*sel1, oacc[n][3]*sel1);
    }
}

// ---------------- launch ----------------
extern "C" void kernel_launch(void* const* d_in, const int* in_sizes, int n_in,
                              void* d_out, int out_size) {
    (void)in_sizes; (void)n_in; (void)out_size;
    const float* q   = (const float*)d_in[0];
    const float* k   = (const float*)d_in[1];
    const float* v   = (const float*)d_in[2];
    const int*   qm  = (const int*)d_in[3];
    const int*   km  = (const int*)d_in[4];
    const int*   vm  = (const int*)d_in[5];
    const float* Wq  = (const float*)d_in[6];
    const float* bq  = (const float*)d_in[7];
    const float* Wk  = (const float*)d_in[8];
    const float* bk  = (const float*)d_in[9];
    const float* Wv  = (const float*)d_in[10];
    const float* bv  = (const float*)d_in[11];
    const float* Wo  = (const float*)d_in[12];
    const float* bo  = (const float*)d_in[13];
    const float* gq  = (const float*)d_in[14];
    const float* bgq = (const float*)d_in[15];
    const float* gk  = (const float*)d_in[16];
    const float* bgk = (const float*)d_in[17];
    const float* gv  = (const float*)d_in[18];
    const float* bgv = (const float*)d_in[19];

    __half *wh, *xT, *qh, *kh, *vh, *kmh, *aT;
    cudaGetSymbolAddress((void**)&wh, g_Wh);
    cudaGetSymbolAddress((void**)&xT, g_xT);
    cudaGetSymbolAddress((void**)&qh, g_qh);
    cudaGetSymbolAddress((void**)&kh, g_kh);
    cudaGetSymbolAddress((void**)&vh, g_vh);
    cudaGetSymbolAddress((void**)&kmh, g_kmh);
    cudaGetSymbolAddress((void**)&aT, g_aT);

    cudaFuncSetAttribute((const void*)proj_h_kernel<true>,
                         cudaFuncAttributeMaxDynamicSharedMemorySize, PROJ_SMEM);
    cudaFuncSetAttribute((const void*)proj_h_kernel<false>,
                         cudaFuncAttributeMaxDynamicSharedMemorySize, PROJ_SMEM);

    std_weights_kernel<<<dim3(NE, 4), 128>>>(Wq, Wk, Wv, Wo);
    transpose_mask_kernel<<<dim3(NT/32, NE/32, 6), dim3(32, 8)>>>(q, k, v, qm, km, vm);
    mask_half_kernel<<<NB*NT/256, 256>>>(km);

    const size_t XSL = (size_t)NB*NT*NE;
    ProjArgs A;
    A.s[0] = { xT + 0*XSL, wh + 0*NE*NE, bq, gq, bgq, (void*)qh, 1, EXP_C, nullptr };
    A.s[1] = { xT + 1*XSL, wh + 1*NE*NE, bk, gk, bgk, (void*)kh, 1, 1.0f, nullptr };
    A.s[2] = { xT + 2*XSL, wh + 2*NE*NE, bv, gv, bgv, (void*)vh, 2, 1.0f, km };
    proj_h_kernel<true><<<dim3(NT/128, NH, 6), 256, PROJ_SMEM>>>(A);

    attn_mma_kernel<<<dim3(NT/128, NH, NB), 256>>>(qh, kh, vh, kmh, qm, aT);

    ProjArgs Ao;
    Ao.s[0] = { aT, wh + 3*NE*NE, bo, nullptr, nullptr, d_out, 0, 1.0f, nullptr };
    Ao.s[1] = Ao.s[0];
    Ao.s[2] = Ao.s[0];
    proj_h_kernel<false><<<dim3(NT/128, NH, 2), 256, PROJ_SMEM>>>(Ao);
}

// round 14
// speedup vs baseline: 1.0392x; 1.0392x over previous
#include <cuda_runtime.h>
#include <cuda_fp16.h>
#include <math.h>

#define NB 2
#define NE 512
#define NH 8
#define ND 64
#define NT 2048
#define EPSV 1e-5f
// exp(s/181) = ex2(s * log2(e)/181); folded into Q at projection time
#define EXP_C (1.44269504088896341f/181.0f)

// ---------------- scratch (device globals: allocation-free) ----------------
__device__ __half g_Wh[4*NE*NE];        // standardized weights, half, [mat][m][e]
__device__ __half g_xT[3*NB*NT*NE];     // masked transposed inputs [which][b][t][e]
__device__ __half g_qh[NB*NH*NT*ND];    // Q transposed (pre-scaled by EXP_C): [b][h][t][d]
__device__ __half g_kh[NB*NH*NT*ND];    // K transposed: [b][h][t][d]
__device__ __half g_vh[NB*NE*NT];       // V (key-masked): [b][e][t]
__device__ __half g_kmh[NB*NT];         // key_mask as half
__device__ __half g_aT[NB*NT*NE];       // attention out transposed [b][t][e]

__device__ __forceinline__ float ex2a(float x) {
    float y;
    asm("ex2.approx.f32 %0, %1;" : "=f"(y) : "f"(x));
    return y;
}
// pack two fp32 -> half2 (lo = first arg)
__device__ __forceinline__ unsigned packh2(float lo, float hi) {
    unsigned r;
    asm("cvt.rn.f16x2.f32 %0, %1, %2;" : "=r"(r) : "f"(hi), "f"(lo));
    return r;
}
__device__ __forceinline__ void mma_f16(float* d,
        unsigned a0, unsigned a1, unsigned a2, unsigned a3,
        unsigned b0, unsigned b1) {
    asm volatile("mma.sync.aligned.m16n8k16.row.col.f32.f16.f16.f32 "
        "{%0,%1,%2,%3}, {%4,%5,%6,%7}, {%8,%9}, {%0,%1,%2,%3};\n"
        : "+f"(d[0]), "+f"(d[1]), "+f"(d[2]), "+f"(d[3])
        : "r"(a0), "r"(a1), "r"(a2), "r"(a3), "r"(b0), "r"(b1));
}
__device__ __forceinline__ void ldsm4(unsigned& r0, unsigned& r1, unsigned& r2, unsigned& r3,
                                      unsigned a) {
    asm volatile("ldmatrix.sync.aligned.m8n8.x4.shared.b16 {%0,%1,%2,%3}, [%4];"
        : "=r"(r0), "=r"(r1), "=r"(r2), "=r"(r3) : "r"(a));
}
__device__ __forceinline__ void ldsm2(unsigned& r0, unsigned& r1, unsigned a) {
    asm volatile("ldmatrix.sync.aligned.m8n8.x2.shared.b16 {%0,%1}, [%2];"
        : "=r"(r0), "=r"(r1) : "r"(a));
}
__device__ __forceinline__ void cp16(void* dst, const void* src) {
    unsigned d = (unsigned)__cvta_generic_to_shared(dst);
    asm volatile("cp.async.ca.shared.global [%0], [%1], 16;" :: "r"(d), "l"(src));
}
__device__ __forceinline__ void cp_commit() { asm volatile("cp.async.commit_group;"); }
__device__ __forceinline__ void cp_wait0()  { asm volatile("cp.async.wait_group 0;"); }

// ---------------- 1) weight standardization (writes half) ----------------
__global__ void std_weights_kernel(const float* __restrict__ W0, const float* __restrict__ W1,
                                   const float* __restrict__ W2, const float* __restrict__ W3) {
    const float* Ws[4] = {W0, W1, W2, W3};
    const float* W = Ws[blockIdx.y];
    __half* out = g_Wh + blockIdx.y * NE * NE;
    const int row = blockIdx.x;
    const int tid = threadIdx.x;

    float w[4];
    #pragma unroll
    for (int j = 0; j < 4; j++) w[j] = W[row*NE + tid + 128*j];

    __shared__ float red[4];
    float s = w[0]+w[1]+w[2]+w[3];
    #pragma unroll
    for (int o = 16; o > 0; o >>= 1) s += __shfl_down_sync(0xffffffffu, s, o);
    if ((tid & 31) == 0) red[tid >> 5] = s;
    __syncthreads();
    const float mu = (red[0]+red[1]+red[2]+red[3]) * (1.0f/NE);
    __syncthreads();

    float s2 = 0.f;
    #pragma unroll
    for (int j = 0; j < 4; j++) { float d = w[j]-mu; s2 += d*d; }
    #pragma unroll
    for (int o = 16; o > 0; o >>= 1) s2 += __shfl_down_sync(0xffffffffu, s2, o);
    if ((tid & 31) == 0) red[tid >> 5] = s2;
    __syncthreads();
    const float var = (red[0]+red[1]+red[2]+red[3]) * (1.0f/NE);
    const float rstd = rsqrtf(var + EPSV);
    #pragma unroll
    for (int j = 0; j < 4; j++)
        out[row*NE + tid + 128*j] = __float2half_rn((w[j]-mu)*rstd);
}

// ---------------- 1b) masked transpose + key-mask-to-half (folded) ----------------
__global__ void transpose_mask_kernel(const float* __restrict__ x0, const float* __restrict__ x1,
                                      const float* __restrict__ x2,
                                      const int* __restrict__ m0, const int* __restrict__ m1,
                                      const int* __restrict__ m2) {
    const int which = blockIdx.z >> 1;
    const int b = blockIdx.z & 1;
    const float* X = (which == 0) ? x0 : (which == 1) ? x1 : x2;
    const int*   M = (which == 0) ? m0 : (which == 1) ? m1 : m2;
    __half* O = g_xT + ((size_t)which*NB + b)*NT*NE;

    __shared__ float tile[32][33];
    const int t0 = blockIdx.x*32, e0 = blockIdx.y*32;
    const int tx = threadIdx.x, ty = threadIdx.y;

    // fold key-mask -> half (once, by which==1 / e0==0 / ty==0 threads)
    if (which == 1 && blockIdx.y == 0 && ty == 0)
        g_kmh[b*NT + t0 + tx] = __float2half_rn((float)M[b*NT + t0 + tx]);

    #pragma unroll
    for (int i = 0; i < 4; i++)
        tile[ty+8*i][tx] = X[(size_t)(b*NE + e0 + ty + 8*i)*NT + t0 + tx];
    __syncthreads();
    #pragma unroll
    for (int i = 0; i < 4; i++) {
        const int t = t0 + ty + 8*i;
        const float mk = (float)M[b*NT + t];
        O[(size_t)t*NE + e0 + tx] = __float2half_rn(tile[tx][ty+8*i]*mk);
    }
}

// ---------------- 2/4) projection GEMM: fp16 mma + ldmatrix, BK=64, 2-stage ----------------
// mode 1: LN*oscale + transposed half out [b][h][t][64]  (Q: oscale=EXP_C; K: 1)
// mode 2: LN * key_mask + half out [b][e][t]             (V)
// mode 0: fp32 out [b][e][t] + bias                      (final output)
struct ProjSet {
    const __half* bT; const __half* wh; const float* bias;
    const float* lng; const float* lnb; void* out; int mode;
    float oscale; const int* xmask;
};
struct ProjArgs { ProjSet s[3]; };

// BK=64 halves: tile rows hold 64 halves (128B) padded to 144B (36 u32) — LDSM conflict-free
#define PR_S 36
#define WST (64*PR_S)            // 2304 u32 per W stage
#define XST (128*PR_S)           // 4608 u32 per x stage
#define XT_S 136
#define PROJ_SMEM ((2*WST + 2*XST)*4)   // 55296 B (also covers LN tile 64*136*4)

template<bool DO_LN>
__global__ void __launch_bounds__(256, 4) proj_h_kernel(ProjArgs A) {
    const int which = blockIdx.z >> 1;
    const int b = blockIdx.z & 1;
    const __half* __restrict__ Bt = A.s[which].bT + (size_t)b*NT*NE;
    const __half* __restrict__ Wh = A.s[which].wh;
    const float*  __restrict__ Bp = A.s[which].bias;
    const float*  __restrict__ Gp = A.s[which].lng;
    const float*  __restrict__ Lp = A.s[which].lnb;
    void*         __restrict__ Op = A.s[which].out;

    const int h  = blockIdx.y;
    const int t0 = blockIdx.x * 128;
    const int tid = threadIdx.x;
    const int lane = tid & 31;
    const int wid = tid >> 5;
    const int wm = wid & 1, wn = wid >> 1;
    const int g = lane >> 2, t4 = lane & 3;

    extern __shared__ float psm[];
    unsigned* wtb = (unsigned*)psm;        // [2][WST]
    unsigned* xtb = wtb + 2*WST;           // [2][XST]
    __shared__ float lng_s[ND];
    __shared__ float lnb_s[ND];
    __shared__ float red_s[256];

    if (DO_LN && tid < 64) {
        lng_s[tid] = Gp[tid];
        lnb_s[tid] = Lp[tid];
    }

    const __half* Wr = Wh + (size_t)(h*ND)*NE;

    auto prefetch = [&](int c, int s) {
        const int k0 = c*64;
        #pragma unroll
        for (int l = 0; l < 2; l++) {   // W: 64 rows x 128B = 512 cp16
            int idx = tid + 256*l; int r = idx >> 3, c16 = idx & 7;
            cp16((char*)(wtb + s*WST + r*PR_S) + c16*16, Wr + (size_t)r*NE + k0 + c16*8);
        }
        #pragma unroll
        for (int l = 0; l < 4; l++) {   // x: 128 rows x 128B = 1024 cp16
            int idx = tid + 256*l; int r = idx >> 3, c16 = idx & 7;
            cp16((char*)(xtb + s*XST + r*PR_S) + c16*16, Bt + (size_t)(t0 + r)*NE + k0 + c16*8);
        }
    };

    prefetch(0, 0);
    cp_commit();

    // ldmatrix lane->address maps (144B row stride: conflict-free)
    const unsigned w_sh = (unsigned)__cvta_generic_to_shared(wtb);
    const unsigned x_sh = (unsigned)__cvta_generic_to_shared(xtb);
    const unsigned aoff = (unsigned)(((((lane>>3)&1)*8) + (lane&7))*144 + ((lane>>4)&1)*16);
    const unsigned boff = (unsigned)(((((lane>>4)&1)*8) + (lane&7))*144 + ((lane>>3)&1)*16);

    float acc[2][4][4];
    #pragma unroll
    for (int mt = 0; mt < 2; mt++)
        #pragma unroll
        for (int n = 0; n < 4; n++)
            #pragma unroll
            for (int j = 0; j < 4; j++) acc[mt][n][j] = 0.f;

    for (int c = 0; c < 8; c++) {
        const int cur = c & 1;
        cp_wait0();
        __syncthreads();
        if (c + 1 < 8) { prefetch(c+1, cur^1); cp_commit(); }

        const unsigned wb = w_sh + cur*(WST*4);
        const unsigned xb = x_sh + cur*(XST*4);
        #pragma unroll
        for (int sub = 0; sub < 4; sub++) {
            unsigned a[2][4];
            #pragma unroll
            for (int mt = 0; mt < 2; mt++)
                ldsm4(a[mt][0], a[mt][1], a[mt][2], a[mt][3],
                      wb + (wm*32 + mt*16)*144 + sub*32 + aoff);
            #pragma unroll
            for (int ng = 0; ng < 2; ng++) {
                unsigned b0a, b1a, b0b, b1b;
                ldsm4(b0a, b1a, b0b, b1b, xb + (wn*32 + ng*16)*144 + sub*32 + boff);
                #pragma unroll
                for (int mt = 0; mt < 2; mt++) {
                    mma_f16(acc[mt][ng*2  ], a[mt][0], a[mt][1], a[mt][2], a[mt][3], b0a, b1a);
                    mma_f16(acc[mt][ng*2+1], a[mt][0], a[mt][1], a[mt][2], a[mt][3], b0b, b1b);
                }
            }
        }
    }

    float bv[2][2];
    #pragma unroll
    for (int mt = 0; mt < 2; mt++) {
        bv[mt][0] = Bp[h*ND + wm*32 + mt*16 + g];
        bv[mt][1] = Bp[h*ND + wm*32 + mt*16 + g + 8];
    }

    if (!DO_LN) {
        float* o = (float*)Op + (size_t)(b*NE + h*ND)*NT + t0;
        #pragma unroll
        for (int mt = 0; mt < 2; mt++) {
            const int r0 = wm*32 + mt*16 + g;
            #pragma unroll
            for (int n = 0; n < 4; n++) {
                const int cc = wn*32 + n*8 + 2*t4;
                *(float2*)(o + (size_t)(r0  )*NT + cc) =
                    make_float2(acc[mt][n][0] + bv[mt][0], acc[mt][n][1] + bv[mt][0]);
                *(float2*)(o + (size_t)(r0+8)*NT + cc) =
                    make_float2(acc[mt][n][2] + bv[mt][1], acc[mt][n][3] + bv[mt][1]);
            }
        }
    } else {
        __syncthreads();   // done with pipeline buffers; reuse psm as [64][136] fp32 tile
        #pragma unroll
        for (int mt = 0; mt < 2; mt++) {
            const int r0 = wm*32 + mt*16 + g;
            #pragma unroll
            for (int n = 0; n < 4; n++) {
                const int cc = wn*32 + n*8 + 2*t4;
                *(float2*)(psm + (r0  )*XT_S + cc) =
                    make_float2(acc[mt][n][0] + bv[mt][0], acc[mt][n][1] + bv[mt][0]);
                *(float2*)(psm + (r0+8)*XT_S + cc) =
                    make_float2(acc[mt][n][2] + bv[mt][1], acc[mt][n][3] + bv[mt][1]);
            }
        }
        __syncthreads();
        // parallel LN: 256 threads, thread owns 32 rows of column cc
        const int cc = tid & 127, hf = tid >> 7;
        const int d0 = hf*32;
        float s = 0.f;
        #pragma unroll 8
        for (int d = 0; d < 32; d++) s += psm[(d0+d)*XT_S + cc];
        red_s[tid] = s;
        __syncthreads();
        const float mu = (red_s[cc] + red_s[128+cc]) * (1.0f/64.0f);
        __syncthreads();
        float s2 = 0.f;
        #pragma unroll 8
        for (int d = 0; d < 32; d++) { float dd = psm[(d0+d)*XT_S + cc] - mu; s2 += dd*dd; }
        red_s[tid] = s2;
        __syncthreads();
        const float rstd = rsqrtf((red_s[cc] + red_s[128+cc])*(1.0f/64.0f) + EPSV);
        const int mode = A.s[which].mode;
        if (mode == 1) {
            const float osc = A.s[which].oscale;
            __half2* dst = (__half2*)((__half*)Op + ((size_t)((b*NH + h)*NT) + t0 + cc)*64);
            #pragma unroll 8
            for (int d2 = hf*16; d2 < hf*16 + 16; d2++) {
                float x0 = ((psm[(2*d2  )*XT_S + cc] - mu)*rstd*lng_s[2*d2  ] + lnb_s[2*d2  ])*osc;
                float x1 = ((psm[(2*d2+1)*XT_S + cc] - mu)*rstd*lng_s[2*d2+1] + lnb_s[2*d2+1])*osc;
                dst[d2] = __floats2half2_rn(x0, x1);
            }
        } else {
            // V: multiply by key_mask so attention needs no score masking
            const float kmv = (float)A.s[which].xmask[b*NT + t0 + cc];
            __half* dst = (__half*)Op + (size_t)(b*NE + h*ND)*NT + t0 + cc;
            #pragma unroll 8
            for (int d = d0; d < d0 + 32; d++)
                dst[(size_t)d*NT] =
                    __float2half_rn(((psm[d*XT_S + cc] - mu)*rstd*lng_s[d] + lnb_s[d])*kmv);
        }
    }
}

// ---------------- 3) flash attention: fp16 mma + ldmatrix + rs-by-matmul ----------------
// grid (T/128, H, B), 256 thr = 8 warps; warp w owns q-rows [w*16, w*16+16).
// K tile: 64 rows x 72 halves (row=key, col=d). V tile: 72 rows x 72 halves
// (rows 0..63 = d, row 64 = key_mask, rows 65..71 = 0); stride 144B => LDSM conflict-free.
// Q pre-scaled by log2e/181 => p = ex2(sf) directly; V key-masked => no score mask;
// oacc n-tile 8 col 64 accumulates the softmax denominator.
#define KV_S2 36
#define KTILE (64*KV_S2)
#define VTILE (72*KV_S2)

__global__ void __launch_bounds__(256, 2) attn_mma_kernel(
        const __half* __restrict__ qh, const __half* __restrict__ kh, const __half* __restrict__ vh,
        const __half* __restrict__ kmh, const int* __restrict__ qmask,
        __half* __restrict__ aT) {
    __shared__ unsigned kh2[2*KTILE];
    __shared__ unsigned vh2[2*VTILE];

    const int t0 = blockIdx.x * 128;
    const int h = blockIdx.y, b = blockIdx.z;
    const int tid = threadIdx.x;
    const int lane = tid & 31;
    const int w = tid >> 5;
    const int g = lane >> 2;
    const int t4 = lane & 3;
    const int w16 = w * 16;
    const int base  = (b*NE + h*ND)*NT;
    const int baseq = ((b*NH + h)*NT);

    // zero V rows 65..71 (both stages) — never touched by cp.async afterwards
    for (int i = tid; i < 2*7*KV_S2; i += 256) {
        int s = i / (7*KV_S2), r = i - s*(7*KV_S2);
        vh2[s*VTILE + 65*KV_S2 + r] = 0;
    }

    // Q fragments straight from gmem (transposed [t][64], pre-scaled)
    const __half* q0 = qh + (size_t)(baseq + t0 + w16 + g)*64;
    const __half* q1 = q0 + 8*64;
    unsigned qa[4][4];
    #pragma unroll
    for (int kc = 0; kc < 4; kc++) {
        qa[kc][0] = *(const unsigned*)(q0 + 16*kc + 2*t4);
        qa[kc][1] = *(const unsigned*)(q1 + 16*kc + 2*t4);
        qa[kc][2] = *(const unsigned*)(q0 + 16*kc + 2*t4 + 8);
        qa[kc][3] = *(const unsigned*)(q1 + 16*kc + 2*t4 + 8);
    }

    auto prefetch = [&](int kt, int s) {
        const int tk0 = kt*64;
        #pragma unroll
        for (int l = 0; l < 2; l++) {
            int idx = tid + 256*l;
            int row = idx >> 3, c16 = idx & 7;
            cp16((char*)(kh2 + s*KTILE + row*KV_S2) + c16*16,
                 kh + (size_t)(baseq + tk0 + row)*64 + c16*8);
            cp16((char*)(vh2 + s*VTILE + row*KV_S2) + c16*16,
                 vh + (size_t)(base + row*NT) + tk0 + c16*8);
        }
        if (tid < 8)
            cp16((char*)(vh2 + s*VTILE + 64*KV_S2) + tid*16, kmh + b*NT + tk0 + tid*8);
    };

    prefetch(0, 0);
    cp_commit();

    const unsigned ks_sh = (unsigned)__cvta_generic_to_shared(kh2);
    const unsigned vs_sh = (unsigned)__cvta_generic_to_shared(vh2);
    const int mm = lane >> 3, rr = lane & 7;
    const unsigned rowoff  = (unsigned)((((mm>>1)*8 + rr)*144) + (mm&1)*16);
    const unsigned rowoff2 = (unsigned)(((64 + rr)*144) + (mm&1)*16);

    float oacc[9][4];
    #pragma unroll
    for (int n = 0; n < 9; n++)
        #pragma unroll
        for (int j = 0; j < 4; j++) oacc[n][j] = 0.f;

    for (int kt = 0; kt < NT/64; kt++) {
        const int cur = kt & 1;
        cp_wait0();
        __syncthreads();
        if (kt + 1 < NT/64) { prefetch(kt+1, cur^1); cp_commit(); }

        const unsigned ksb = ks_sh + cur*KTILE*4 + rowoff;
        const unsigned vsb = vs_sh + cur*VTILE*4;

        // ---- S = Q K^T (scaled) ----
        float sf[8][4];
        #pragma unroll
        for (int n = 0; n < 8; n++)
            #pragma unroll
            for (int j = 0; j < 4; j++) sf[n][j] = 0.f;
        #pragma unroll
        for (int kc = 0; kc < 4; kc++) {
            #pragma unroll
            for (int j = 0; j < 4; j++) {
                unsigned b0a, b1a, b0b, b1b;
                ldsm4(b0a, b1a, b0b, b1b, ksb + j*2304 + kc*32);
                mma_f16(sf[2*j  ], qa[kc][0], qa[kc][1], qa[kc][2], qa[kc][3], b0a, b1a);
                mma_f16(sf[2*j+1], qa[kc][0], qa[kc][1], qa[kc][2], qa[kc][3], b0b, b1b);
            }
        }

        // ---- p = ex2(sf) (unmasked; V carries the mask), pack to A fragments ----
        unsigned plo[8], phi[8];
        #pragma unroll
        for (int n = 0; n < 8; n++) {
            plo[n] = packh2(ex2a(sf[n][0]), ex2a(sf[n][1]));
            phi[n] = packh2(ex2a(sf[n][2]), ex2a(sf[n][3]));
        }

        // ---- O += P V^T (+ mask-row tile accumulates denominator) ----
        #pragma unroll
        for (int kc = 0; kc < 4; kc++) {
            unsigned a0 = plo[2*kc], a1 = phi[2*kc], a2 = plo[2*kc+1], a3 = phi[2*kc+1];
            #pragma unroll
            for (int j = 0; j < 4; j++) {
                unsigned b0a, b1a, b0b, b1b;
                ldsm4(b0a, b1a, b0b, b1b, vsb + rowoff + j*2304 + kc*32);
                mma_f16(oacc[2*j  ], a0, a1, a2, a3, b0a, b1a);
                mma_f16(oacc[2*j+1], a0, a1, a2, a3, b0b, b1b);
            }
            unsigned m0, m1;
            ldsm2(m0, m1, vsb + rowoff2 + kc*32);
            mma_f16(oacc[8], a0, a1, a2, a3, m0, m1);
        }
    }

    // ---- denominator from mask-tile col 64 (t4==0 slot), broadcast in quad ----
    const float rs0 = __shfl_sync(0xffffffffu, oacc[8][0], lane & ~3);
    const float rs1 = __shfl_sync(0xffffffffu, oacc[8][2], lane & ~3);

    const int qrow0 = t0 + w16 + g;
    const int qrow1 = qrow0 + 8;
    const float sel0 = (qmask[b*NT + qrow0] != 0) ? (1.0f / rs0) : 0.f;
    const float sel1 = (qmask[b*NT + qrow1] != 0) ? (1.0f / rs1) : 0.f;
    __half* o0 = aT + (size_t)(b*NT + qrow0)*NE + h*ND;
    __half* o1 = aT + (size_t)(b*NT + qrow1)*NE + h*ND;
    #pragma unroll
    for (int n = 0; n < 8; n++) {
        const int d0 = n*8 + 2*t4;
        *(unsigned*)(o0 + d0) = packh2(oacc[n][0]*sel0, oacc[n][1]*sel0);
        *(unsigned*)(o1 + d0) = packh2(oacc[n][2]*sel1, oacc[n][3]*sel1);
    }
}

// ---------------- launch ----------------
extern "C" void kernel_launch(void* const* d_in, const int* in_sizes, int n_in,
                              void* d_out, int out_size) {
    (void)in_sizes; (void)n_in; (void)out_size;
    const float* q   = (const float*)d_in[0];
    const float* k   = (const float*)d_in[1];
    const float* v   = (const float*)d_in[2];
    const int*   qm  = (const int*)d_in[3];
    const int*   km  = (const int*)d_in[4];
    const int*   vm  = (const int*)d_in[5];
    const float* Wq  = (const float*)d_in[6];
    const float* bq  = (const float*)d_in[7];
    const float* Wk  = (const float*)d_in[8];
    const float* bk  = (const float*)d_in[9];
    const float* Wv  = (const float*)d_in[10];
    const float* bv  = (const float*)d_in[11];
    const float* Wo  = (const float*)d_in[12];
    const float* bo  = (const float*)d_in[13];
    const float* gq  = (const float*)d_in[14];
    const float* bgq = (const float*)d_in[15];
    const float* gk  = (const float*)d_in[16];
    const float* bgk = (const float*)d_in[17];
    const float* gv  = (const float*)d_in[18];
    const float* bgv = (const float*)d_in[19];

    __half *wh, *xT, *qh, *kh, *vh, *kmh, *aT;
    cudaGetSymbolAddress((void**)&wh, g_Wh);
    cudaGetSymbolAddress((void**)&xT, g_xT);
    cudaGetSymbolAddress((void**)&qh, g_qh);
    cudaGetSymbolAddress((void**)&kh, g_kh);
    cudaGetSymbolAddress((void**)&vh, g_vh);
    cudaGetSymbolAddress((void**)&kmh, g_kmh);
    cudaGetSymbolAddress((void**)&aT, g_aT);

    cudaFuncSetAttribute((const void*)proj_h_kernel<true>,
                         cudaFuncAttributeMaxDynamicSharedMemorySize, PROJ_SMEM);
    cudaFuncSetAttribute((const void*)proj_h_kernel<false>,
                         cudaFuncAttributeMaxDynamicSharedMemorySize, PROJ_SMEM);

    std_weights_kernel<<<dim3(NE, 4), 128>>>(Wq, Wk, Wv, Wo);
    transpose_mask_kernel<<<dim3(NT/32, NE/32, 6), dim3(32, 8)>>>(q, k, v, qm, km, vm);

    const size_t XSL = (size_t)NB*NT*NE;
    ProjArgs A;
    A.s[0] = { xT + 0*XSL, wh + 0*NE*NE, bq, gq, bgq, (void*)qh, 1, EXP_C, nullptr };
    A.s[1] = { xT + 1*XSL, wh + 1*NE*NE, bk, gk, bgk, (void*)kh, 1, 1.0f, nullptr };
    A.s[2] = { xT + 2*XSL, wh + 2*NE*NE, bv, gv, bgv, (void*)vh, 2, 1.0f, km };
    proj_h_kernel<true><<<dim3(NT/128, NH, 6), 256, PROJ_SMEM>>>(A);

    attn_mma_kernel<<<dim3(NT/128, NH, NB), 256>>>(qh, kh, vh, kmh, qm, aT);

    ProjArgs Ao;
    Ao.s[0] = { aT, wh + 3*NE*NE, bo, nullptr, nullptr, d_out, 0, 1.0f, nullptr };
    Ao.s[1] = Ao.s[0];
    Ao.s[2] = Ao.s[0];
    proj_h_kernel<false><<<dim3(NT/128, NH, 2), 256, PROJ_SMEM>>>(Ao);
}

// round 15
// speedup vs baseline: 1.0738x; 1.0334x over previous
#include <cuda_runtime.h>
#include <cuda_fp16.h>
#include <math.h>

#define NB 2
#define NE 512
#define NH 8
#define ND 64
#define NT 2048
#define EPSV 1e-5f
// exp(s/181) = ex2(s * log2(e)/181); folded into Q at projection time
#define EXP_C (1.44269504088896341f/181.0f)

// ---------------- scratch (device globals: allocation-free) ----------------
__device__ __half g_Wh[4*NE*NE];        // standardized weights, half, [mat][m][e]
__device__ __half g_xT[3*NB*NT*NE];     // masked transposed inputs [which][b][t][e]
__device__ __half g_qh[NB*NH*NT*ND];    // Q transposed (pre-scaled by EXP_C): [b][h][t][d]
__device__ __half g_kh[NB*NH*NT*ND];    // K transposed: [b][h][t][d]
__device__ __half g_vh[NB*NE*NT];       // V (key-masked): [b][e][t]
__device__ __half g_kmh[NB*NT];         // key_mask as half
__device__ __half g_aT[NB*NT*NE];       // attention out transposed [b][t][e]

__device__ __forceinline__ float ex2a(float x) {
    float y;
    asm("ex2.approx.f32 %0, %1;" : "=f"(y) : "f"(x));
    return y;
}
// pack two fp32 -> half2 (lo = first arg)
__device__ __forceinline__ unsigned packh2(float lo, float hi) {
    unsigned r;
    asm("cvt.rn.f16x2.f32 %0, %1, %2;" : "=r"(r) : "f"(hi), "f"(lo));
    return r;
}
__device__ __forceinline__ void mma_f16(float* d,
        unsigned a0, unsigned a1, unsigned a2, unsigned a3,
        unsigned b0, unsigned b1) {
    asm volatile("mma.sync.aligned.m16n8k16.row.col.f32.f16.f16.f32 "
        "{%0,%1,%2,%3}, {%4,%5,%6,%7}, {%8,%9}, {%0,%1,%2,%3};\n"
        : "+f"(d[0]), "+f"(d[1]), "+f"(d[2]), "+f"(d[3])
        : "r"(a0), "r"(a1), "r"(a2), "r"(a3), "r"(b0), "r"(b1));
}
__device__ __forceinline__ void ldsm4(unsigned& r0, unsigned& r1, unsigned& r2, unsigned& r3,
                                      unsigned a) {
    asm volatile("ldmatrix.sync.aligned.m8n8.x4.shared.b16 {%0,%1,%2,%3}, [%4];"
        : "=r"(r0), "=r"(r1), "=r"(r2), "=r"(r3) : "r"(a));
}
__device__ __forceinline__ void ldsm2(unsigned& r0, unsigned& r1, unsigned a) {
    asm volatile("ldmatrix.sync.aligned.m8n8.x2.shared.b16 {%0,%1}, [%2];"
        : "=r"(r0), "=r"(r1) : "r"(a));
}
__device__ __forceinline__ void cp16(void* dst, const void* src) {
    unsigned d = (unsigned)__cvta_generic_to_shared(dst);
    asm volatile("cp.async.ca.shared.global [%0], [%1], 16;" :: "r"(d), "l"(src));
}
__device__ __forceinline__ void cp_commit() { asm volatile("cp.async.commit_group;"); }
__device__ __forceinline__ void cp_wait0()  { asm volatile("cp.async.wait_group 0;"); }

// ---------------- 1) weight standardization (writes half) ----------------
__global__ void std_weights_kernel(const float* __restrict__ W0, const float* __restrict__ W1,
                                   const float* __restrict__ W2, const float* __restrict__ W3) {
    const float* Ws[4] = {W0, W1, W2, W3};
    const float* W = Ws[blockIdx.y];
    __half* out = g_Wh + blockIdx.y * NE * NE;
    const int row = blockIdx.x;
    const int tid = threadIdx.x;

    float w[4];
    #pragma unroll
    for (int j = 0; j < 4; j++) w[j] = W[row*NE + tid + 128*j];

    __shared__ float red[4];
    float s = w[0]+w[1]+w[2]+w[3];
    #pragma unroll
    for (int o = 16; o > 0; o >>= 1) s += __shfl_down_sync(0xffffffffu, s, o);
    if ((tid & 31) == 0) red[tid >> 5] = s;
    __syncthreads();
    const float mu = (red[0]+red[1]+red[2]+red[3]) * (1.0f/NE);
    __syncthreads();

    float s2 = 0.f;
    #pragma unroll
    for (int j = 0; j < 4; j++) { float d = w[j]-mu; s2 += d*d; }
    #pragma unroll
    for (int o = 16; o > 0; o >>= 1) s2 += __shfl_down_sync(0xffffffffu, s2, o);
    if ((tid & 31) == 0) red[tid >> 5] = s2;
    __syncthreads();
    const float var = (red[0]+red[1]+red[2]+red[3]) * (1.0f/NE);
    const float rstd = rsqrtf(var + EPSV);
    #pragma unroll
    for (int j = 0; j < 4; j++)
        out[row*NE + tid + 128*j] = __float2half_rn((w[j]-mu)*rstd);
}

// ---------------- 1b) masked transpose + key-mask-to-half (folded) ----------------
__global__ void transpose_mask_kernel(const float* __restrict__ x0, const float* __restrict__ x1,
                                      const float* __restrict__ x2,
                                      const int* __restrict__ m0, const int* __restrict__ m1,
                                      const int* __restrict__ m2) {
    const int which = blockIdx.z >> 1;
    const int b = blockIdx.z & 1;
    const float* X = (which == 0) ? x0 : (which == 1) ? x1 : x2;
    const int*   M = (which == 0) ? m0 : (which == 1) ? m1 : m2;
    __half* O = g_xT + ((size_t)which*NB + b)*NT*NE;

    __shared__ float tile[32][33];
    const int t0 = blockIdx.x*32, e0 = blockIdx.y*32;
    const int tx = threadIdx.x, ty = threadIdx.y;

    // fold key-mask -> half (once, by which==1 / e0==0 / ty==0 threads)
    if (which == 1 && blockIdx.y == 0 && ty == 0)
        g_kmh[b*NT + t0 + tx] = __float2half_rn((float)M[b*NT + t0 + tx]);

    #pragma unroll
    for (int i = 0; i < 4; i++)
        tile[ty+8*i][tx] = X[(size_t)(b*NE + e0 + ty + 8*i)*NT + t0 + tx];
    __syncthreads();
    #pragma unroll
    for (int i = 0; i < 4; i++) {
        const int t = t0 + ty + 8*i;
        const float mk = (float)M[b*NT + t];
        O[(size_t)t*NE + e0 + tx] = __float2half_rn(tile[tx][ty+8*i]*mk);
    }
}

// ---------------- 2/4) projection GEMM: fp16 mma + ldmatrix, BK=64, 2-stage (R11 config) ----------------
struct ProjSet {
    const __half* bT; const __half* wh; const float* bias;
    const float* lng; const float* lnb; void* out; int mode;
    float oscale; const int* xmask;
};
struct ProjArgs { ProjSet s[3]; };

#define PR_S 36
#define WST (64*PR_S)            // 2304 u32 per W stage
#define XST (128*PR_S)           // 4608 u32 per x stage
#define XT_S 136
#define PROJ_SMEM ((2*WST + 2*XST)*4)   // 55296 B (also covers LN tile 64*136*4)

template<bool DO_LN>
__global__ void __launch_bounds__(256) proj_h_kernel(ProjArgs A) {
    const int which = blockIdx.z >> 1;
    const int b = blockIdx.z & 1;
    const __half* __restrict__ Bt = A.s[which].bT + (size_t)b*NT*NE;
    const __half* __restrict__ Wh = A.s[which].wh;
    const float*  __restrict__ Bp = A.s[which].bias;
    const float*  __restrict__ Gp = A.s[which].lng;
    const float*  __restrict__ Lp = A.s[which].lnb;
    void*         __restrict__ Op = A.s[which].out;

    const int h  = blockIdx.y;
    const int t0 = blockIdx.x * 128;
    const int tid = threadIdx.x;
    const int lane = tid & 31;
    const int wid = tid >> 5;
    const int wm = wid & 1, wn = wid >> 1;
    const int g = lane >> 2, t4 = lane & 3;

    extern __shared__ float psm[];
    unsigned* wtb = (unsigned*)psm;        // [2][WST]
    unsigned* xtb = wtb + 2*WST;           // [2][XST]
    __shared__ float lng_s[ND];
    __shared__ float lnb_s[ND];
    __shared__ float red_s[256];

    if (DO_LN && tid < 64) {
        lng_s[tid] = Gp[tid];
        lnb_s[tid] = Lp[tid];
    }

    const __half* Wr = Wh + (size_t)(h*ND)*NE;

    auto prefetch = [&](int c, int s) {
        const int k0 = c*64;
        #pragma unroll
        for (int l = 0; l < 2; l++) {   // W: 64 rows x 128B = 512 cp16
            int idx = tid + 256*l; int r = idx >> 3, c16 = idx & 7;
            cp16((char*)(wtb + s*WST + r*PR_S) + c16*16, Wr + (size_t)r*NE + k0 + c16*8);
        }
        #pragma unroll
        for (int l = 0; l < 4; l++) {   // x: 128 rows x 128B = 1024 cp16
            int idx = tid + 256*l; int r = idx >> 3, c16 = idx & 7;
            cp16((char*)(xtb + s*XST + r*PR_S) + c16*16, Bt + (size_t)(t0 + r)*NE + k0 + c16*8);
        }
    };

    prefetch(0, 0);
    cp_commit();

    // ldmatrix lane->address maps (144B row stride: conflict-free)
    const unsigned w_sh = (unsigned)__cvta_generic_to_shared(wtb);
    const unsigned x_sh = (unsigned)__cvta_generic_to_shared(xtb);
    const unsigned aoff = (unsigned)(((((lane>>3)&1)*8) + (lane&7))*144 + ((lane>>4)&1)*16);
    const unsigned boff = (unsigned)(((((lane>>4)&1)*8) + (lane&7))*144 + ((lane>>3)&1)*16);

    float acc[2][4][4];
    #pragma unroll
    for (int mt = 0; mt < 2; mt++)
        #pragma unroll
        for (int n = 0; n < 4; n++)
            #pragma unroll
            for (int j = 0; j < 4; j++) acc[mt][n][j] = 0.f;

    for (int c = 0; c < 8; c++) {
        const int cur = c & 1;
        cp_wait0();
        __syncthreads();
        if (c + 1 < 8) { prefetch(c+1, cur^1); cp_commit(); }

        const unsigned wb = w_sh + cur*(WST*4);
        const unsigned xb = x_sh + cur*(XST*4);
        #pragma unroll
        for (int sub = 0; sub < 4; sub++) {
            unsigned a[2][4];
            #pragma unroll
            for (int mt = 0; mt < 2; mt++)
                ldsm4(a[mt][0], a[mt][1], a[mt][2], a[mt][3],
                      wb + (wm*32 + mt*16)*144 + sub*32 + aoff);
            #pragma unroll
            for (int ng = 0; ng < 2; ng++) {
                unsigned b0a, b1a, b0b, b1b;
                ldsm4(b0a, b1a, b0b, b1b, xb + (wn*32 + ng*16)*144 + sub*32 + boff);
                #pragma unroll
                for (int mt = 0; mt < 2; mt++) {
                    mma_f16(acc[mt][ng*2  ], a[mt][0], a[mt][1], a[mt][2], a[mt][3], b0a, b1a);
                    mma_f16(acc[mt][ng*2+1], a[mt][0], a[mt][1], a[mt][2], a[mt][3], b0b, b1b);
                }
            }
        }
    }

    float bv[2][2];
    #pragma unroll
    for (int mt = 0; mt < 2; mt++) {
        bv[mt][0] = Bp[h*ND + wm*32 + mt*16 + g];
        bv[mt][1] = Bp[h*ND + wm*32 + mt*16 + g + 8];
    }

    if (!DO_LN) {
        float* o = (float*)Op + (size_t)(b*NE + h*ND)*NT + t0;
        #pragma unroll
        for (int mt = 0; mt < 2; mt++) {
            const int r0 = wm*32 + mt*16 + g;
            #pragma unroll
            for (int n = 0; n < 4; n++) {
                const int cc = wn*32 + n*8 + 2*t4;
                *(float2*)(o + (size_t)(r0  )*NT + cc) =
                    make_float2(acc[mt][n][0] + bv[mt][0], acc[mt][n][1] + bv[mt][0]);
                *(float2*)(o + (size_t)(r0+8)*NT + cc) =
                    make_float2(acc[mt][n][2] + bv[mt][1], acc[mt][n][3] + bv[mt][1]);
            }
        }
    } else {
        __syncthreads();   // done with pipeline buffers; reuse psm as [64][136] fp32 tile
        #pragma unroll
        for (int mt = 0; mt < 2; mt++) {
            const int r0 = wm*32 + mt*16 + g;
            #pragma unroll
            for (int n = 0; n < 4; n++) {
                const int cc = wn*32 + n*8 + 2*t4;
                *(float2*)(psm + (r0  )*XT_S + cc) =
                    make_float2(acc[mt][n][0] + bv[mt][0], acc[mt][n][1] + bv[mt][0]);
                *(float2*)(psm + (r0+8)*XT_S + cc) =
                    make_float2(acc[mt][n][2] + bv[mt][1], acc[mt][n][3] + bv[mt][1]);
            }
        }
        __syncthreads();
        // parallel LN: 256 threads, thread owns 32 rows of column cc
        const int cc = tid & 127, hf = tid >> 7;
        const int d0 = hf*32;
        float s = 0.f;
        #pragma unroll 8
        for (int d = 0; d < 32; d++) s += psm[(d0+d)*XT_S + cc];
        red_s[tid] = s;
        __syncthreads();
        const float mu = (red_s[cc] + red_s[128+cc]) * (1.0f/64.0f);
        __syncthreads();
        float s2 = 0.f;
        #pragma unroll 8
        for (int d = 0; d < 32; d++) { float dd = psm[(d0+d)*XT_S + cc] - mu; s2 += dd*dd; }
        red_s[tid] = s2;
        __syncthreads();
        const float rstd = rsqrtf((red_s[cc] + red_s[128+cc])*(1.0f/64.0f) + EPSV);
        const int mode = A.s[which].mode;
        if (mode == 1) {
            const float osc = A.s[which].oscale;
            __half2* dst = (__half2*)((__half*)Op + ((size_t)((b*NH + h)*NT) + t0 + cc)*64);
            #pragma unroll 8
            for (int d2 = hf*16; d2 < hf*16 + 16; d2++) {
                float x0 = ((psm[(2*d2  )*XT_S + cc] - mu)*rstd*lng_s[2*d2  ] + lnb_s[2*d2  ])*osc;
                float x1 = ((psm[(2*d2+1)*XT_S + cc] - mu)*rstd*lng_s[2*d2+1] + lnb_s[2*d2+1])*osc;
                dst[d2] = __floats2half2_rn(x0, x1);
            }
        } else {
            // V: multiply by key_mask so attention needs no score masking
            const float kmv = (float)A.s[which].xmask[b*NT + t0 + cc];
            __half* dst = (__half*)Op + (size_t)(b*NE + h*ND)*NT + t0 + cc;
            #pragma unroll 8
            for (int d = d0; d < d0 + 32; d++)
                dst[(size_t)d*NT] =
                    __float2half_rn(((psm[d*XT_S + cc] - mu)*rstd*lng_s[d] + lnb_s[d])*kmv);
        }
    }
}

// ---------------- 3) flash attention: fp16 mma + ldmatrix, 128-key staged tiles ----------------
// grid (T/128, H, B), 256 thr = 8 warps; warp w owns q-rows [w*16, w*16+16).
// K tile: 128 rows(keys) x 72 halves (144B stride). V tile: 72 rows x 136 halves
// (272B stride; rows 0..63 = d over 128 keys, row 64 = key_mask, 65..71 = 0).
// Two 64-key sub-chunks per barrier interval => 136 mma between syncs.
#define KV_S2 36                  // K row stride (u32)
#define VV_S2 68                  // V row stride (u32), 272B: conflict-free LDSM
#define KST (128*KV_S2)           // 4608 u32 per K stage
#define VST (72*VV_S2)            // 4896 u32 per V stage
#define ATTN_SMEM ((2*KST + 2*VST)*4)   // 76032 B

__global__ void __launch_bounds__(256, 2) attn_mma_kernel(
        const __half* __restrict__ qh, const __half* __restrict__ kh, const __half* __restrict__ vh,
        const __half* __restrict__ kmh, const int* __restrict__ qmask,
        __half* __restrict__ aT) {
    extern __shared__ unsigned asm_u[];
    unsigned* kh2 = asm_u;            // [2][KST]
    unsigned* vh2 = asm_u + 2*KST;    // [2][VST]

    const int t0 = blockIdx.x * 128;
    const int h = blockIdx.y, b = blockIdx.z;
    const int tid = threadIdx.x;
    const int lane = tid & 31;
    const int w = tid >> 5;
    const int g = lane >> 2;
    const int t4 = lane & 3;
    const int w16 = w * 16;
    const int base  = (b*NE + h*ND)*NT;
    const int baseq = ((b*NH + h)*NT);

    // zero V rows 65..71 (both stages) — never touched by cp.async afterwards
    for (int i = tid; i < 2*7*VV_S2; i += 256) {
        int s = i / (7*VV_S2), r = i - s*(7*VV_S2);
        vh2[s*VST + 65*VV_S2 + r] = 0;
    }

    // Q fragments straight from gmem (transposed [t][64], pre-scaled)
    const __half* q0 = qh + (size_t)(baseq + t0 + w16 + g)*64;
    const __half* q1 = q0 + 8*64;
    unsigned qa[4][4];
    #pragma unroll
    for (int kc = 0; kc < 4; kc++) {
        qa[kc][0] = *(const unsigned*)(q0 + 16*kc + 2*t4);
        qa[kc][1] = *(const unsigned*)(q1 + 16*kc + 2*t4);
        qa[kc][2] = *(const unsigned*)(q0 + 16*kc + 2*t4 + 8);
        qa[kc][3] = *(const unsigned*)(q1 + 16*kc + 2*t4 + 8);
    }

    // prefetch one 128-key tile into stage s
    auto prefetch = [&](int kt, int s) {
        const int tk0 = kt*128;
        #pragma unroll
        for (int l = 0; l < 4; l++) {   // K: 128 rows x 128B = 1024 cp16
            int idx = tid + 256*l;
            int row = idx >> 3, c16 = idx & 7;
            cp16((char*)(kh2 + s*KST + row*KV_S2) + c16*16,
                 kh + (size_t)(baseq + tk0 + row)*64 + c16*8);
        }
        #pragma unroll
        for (int l = 0; l < 4; l++) {   // V: 64 d-rows x 256B = 1024 cp16
            int idx = tid + 256*l;
            int row = idx >> 4, c16 = idx & 15;
            cp16((char*)(vh2 + s*VST + row*VV_S2) + c16*16,
                 vh + (size_t)(base + row*NT) + tk0 + c16*8);
        }
        if (tid < 16)                   // mask row 64: 128 halves = 16 cp16
            cp16((char*)(vh2 + s*VST + 64*VV_S2) + tid*16, kmh + b*NT + tk0 + tid*8);
    };

    prefetch(0, 0);
    cp_commit();

    const unsigned ks_sh = (unsigned)__cvta_generic_to_shared(kh2);
    const unsigned vs_sh = (unsigned)__cvta_generic_to_shared(vh2);
    const int mm = lane >> 3, rr = lane & 7;
    const unsigned rowoffK  = (unsigned)((((mm>>1)*8 + rr)*144) + (mm&1)*16);
    const unsigned rowoffV  = (unsigned)((((mm>>1)*8 + rr)*272) + (mm&1)*16);
    const unsigned rowoffV2 = (unsigned)(((64 + rr)*272) + (mm&1)*16);

    float oacc[9][4];
    #pragma unroll
    for (int n = 0; n < 9; n++)
        #pragma unroll
        for (int j = 0; j < 4; j++) oacc[n][j] = 0.f;

    for (int kt = 0; kt < NT/128; kt++) {
        const int cur = kt & 1;
        cp_wait0();
        __syncthreads();
        if (kt + 1 < NT/128) { prefetch(kt+1, cur^1); cp_commit(); }

        #pragma unroll
        for (int half = 0; half < 2; half++) {
            const unsigned ksb = ks_sh + cur*(KST*4) + half*(64*144) + rowoffK;
            const unsigned vsb = vs_sh + cur*(VST*4) + half*128;

            // ---- S = Q K^T (scaled) over 64 keys ----
            float sf[8][4];
            #pragma unroll
            for (int n = 0; n < 8; n++)
                #pragma unroll
                for (int j = 0; j < 4; j++) sf[n][j] = 0.f;
            #pragma unroll
            for (int kc = 0; kc < 4; kc++) {
                #pragma unroll
                for (int j = 0; j < 4; j++) {
                    unsigned b0a, b1a, b0b, b1b;
                    ldsm4(b0a, b1a, b0b, b1b, ksb + j*2304 + kc*32);
                    mma_f16(sf[2*j  ], qa[kc][0], qa[kc][1], qa[kc][2], qa[kc][3], b0a, b1a);
                    mma_f16(sf[2*j+1], qa[kc][0], qa[kc][1], qa[kc][2], qa[kc][3], b0b, b1b);
                }
            }

            // ---- p = ex2(sf), pack to A fragments ----
            unsigned plo[8], phi[8];
            #pragma unroll
            for (int n = 0; n < 8; n++) {
                plo[n] = packh2(ex2a(sf[n][0]), ex2a(sf[n][1]));
                phi[n] = packh2(ex2a(sf[n][2]), ex2a(sf[n][3]));
            }

            // ---- O += P V^T (+ mask-row tile accumulates denominator) ----
            #pragma unroll
            for (int kc = 0; kc < 4; kc++) {
                unsigned a0 = plo[2*kc], a1 = phi[2*kc], a2 = plo[2*kc+1], a3 = phi[2*kc+1];
                #pragma unroll
                for (int j = 0; j < 4; j++) {
                    unsigned b0a, b1a, b0b, b1b;
                    ldsm4(b0a, b1a, b0b, b1b, vsb + rowoffV + j*4352 + kc*32);
                    mma_f16(oacc[2*j  ], a0, a1, a2, a3, b0a, b1a);
                    mma_f16(oacc[2*j+1], a0, a1, a2, a3, b0b, b1b);
                }
                unsigned m0, m1;
                ldsm2(m0, m1, vsb + rowoffV2 + kc*32);
                mma_f16(oacc[8], a0, a1, a2, a3, m0, m1);
            }
        }
    }

    // ---- denominator from mask-tile col 64 (t4==0 slot), broadcast in quad ----
    const float rs0 = __shfl_sync(0xffffffffu, oacc[8][0], lane & ~3);
    const float rs1 = __shfl_sync(0xffffffffu, oacc[8][2], lane & ~3);

    const int qrow0 = t0 + w16 + g;
    const int qrow1 = qrow0 + 8;
    const float sel0 = (qmask[b*NT + qrow0] != 0) ? (1.0f / rs0) : 0.f;
    const float sel1 = (qmask[b*NT + qrow1] != 0) ? (1.0f / rs1) : 0.f;
    __half* o0 = aT + (size_t)(b*NT + qrow0)*NE + h*ND;
    __half* o1 = aT + (size_t)(b*NT + qrow1)*NE + h*ND;
    #pragma unroll
    for (int n = 0; n < 8; n++) {
        const int d0 = n*8 + 2*t4;
        *(unsigned*)(o0 + d0) = packh2(oacc[n][0]*sel0, oacc[n][1]*sel0);
        *(unsigned*)(o1 + d0) = packh2(oacc[n][2]*sel1, oacc[n][3]*sel1);
    }
}

// ---------------- launch ----------------
extern "C" void kernel_launch(void* const* d_in, const int* in_sizes, int n_in,
                              void* d_out, int out_size) {
    (void)in_sizes; (void)n_in; (void)out_size;
    const float* q   = (const float*)d_in[0];
    const float* k   = (const float*)d_in[1];
    const float* v   = (const float*)d_in[2];
    const int*   qm  = (const int*)d_in[3];
    const int*   km  = (const int*)d_in[4];
    const int*   vm  = (const int*)d_in[5];
    const float* Wq  = (const float*)d_in[6];
    const float* bq  = (const float*)d_in[7];
    const float* Wk  = (const float*)d_in[8];
    const float* bk  = (const float*)d_in[9];
    const float* Wv  = (const float*)d_in[10];
    const float* bv  = (const float*)d_in[11];
    const float* Wo  = (const float*)d_in[12];
    const float* bo  = (const float*)d_in[13];
    const float* gq  = (const float*)d_in[14];
    const float* bgq = (const float*)d_in[15];
    const float* gk  = (const float*)d_in[16];
    const float* bgk = (const float*)d_in[17];
    const float* gv  = (const float*)d_in[18];
    const float* bgv = (const float*)d_in[19];

    __half *wh, *xT, *qh, *kh, *vh, *kmh, *aT;
    cudaGetSymbolAddress((void**)&wh, g_Wh);
    cudaGetSymbolAddress((void**)&xT, g_xT);
    cudaGetSymbolAddress((void**)&qh, g_qh);
    cudaGetSymbolAddress((void**)&kh, g_kh);
    cudaGetSymbolAddress((void**)&vh, g_vh);
    cudaGetSymbolAddress((void**)&kmh, g_kmh);
    cudaGetSymbolAddress((void**)&aT, g_aT);

    cudaFuncSetAttribute((const void*)proj_h_kernel<true>,
                         cudaFuncAttributeMaxDynamicSharedMemorySize, PROJ_SMEM);
    cudaFuncSetAttribute((const void*)proj_h_kernel<false>,
                         cudaFuncAttributeMaxDynamicSharedMemorySize, PROJ_SMEM);
    cudaFuncSetAttribute((const void*)attn_mma_kernel,
                         cudaFuncAttributeMaxDynamicSharedMemorySize, ATTN_SMEM);

    std_weights_kernel<<<dim3(NE, 4), 128>>>(Wq, Wk, Wv, Wo);
    transpose_mask_kernel<<<dim3(NT/32, NE/32, 6), dim3(32, 8)>>>(q, k, v, qm, km, vm);

    const size_t XSL = (size_t)NB*NT*NE;
    ProjArgs A;
    A.s[0] = { xT + 0*XSL, wh + 0*NE*NE, bq, gq, bgq, (void*)qh, 1, EXP_C, nullptr };
    A.s[1] = { xT + 1*XSL, wh + 1*NE*NE, bk, gk, bgk, (void*)kh, 1, 1.0f, nullptr };
    A.s[2] = { xT + 2*XSL, wh + 2*NE*NE, bv, gv, bgv, (void*)vh, 2, 1.0f, km };
    proj_h_kernel<true><<<dim3(NT/128, NH, 6), 256, PROJ_SMEM>>>(A);

    attn_mma_kernel<<<dim3(NT/128, NH, NB), 256, ATTN_SMEM>>>(qh, kh, vh, kmh, qm, aT);

    ProjArgs Ao;
    Ao.s[0] = { aT, wh + 3*NE*NE, bo, nullptr, nullptr, d_out, 0, 1.0f, nullptr };
    Ao.s[1] = Ao.s[0];
    Ao.s[2] = Ao.s[0];
    proj_h_kernel<false><<<dim3(NT/128, NH, 2), 256, PROJ_SMEM>>>(Ao);
}